// round 13
// baseline (speedup 1.0000x reference)
#include <cuda_runtime.h>
#include <cstdint>

// ---------------------------------------------------------------------------
// GraphSAGE VGAE encoder, GB300.
//  * NO host-side use of __device__ symbols (all scratch resolved in-kernel)
//  * edge_index dtype (int32 vs int64) sniffed at runtime
//  * scalar memory ops, 1-D launches, int atomics only
// Dataflow (project-then-aggregate; aggregation is linear):
//   z1 = x @ Wl1               agg1 = mean-gather(z1)
//   h1 = relu(x @ Wr1 + agg1 + b1)
//   z2 = h1 @ Wl2              agg2 = mean-gather(z2)
//   h2 = relu(h1 @ Wr2 + agg2 + b2)
//   agg3 = mean-gather(h2)     (shared by both heads)
//   mu = agg3 @ Wlmu + h2 @ Wrmu + bmu
//   lv = agg3 @ Wllv + h2 @ Wrlv + blv
// ---------------------------------------------------------------------------

static constexpr int NODES = 50000;
static constexpr int ED    = 800000;
static constexpr int IN_D  = 128;
static constexpr int D1    = 117;
static constexpr int D2    = 42;
static constexpr int DOUT  = 24;

static constexpr int SCAN_B = 256;
static constexpr int NBLK   = (NODES + SCAN_B - 1) / SCAN_B;   // 196

__device__ float g_z1  [NODES * D1];
__device__ float g_agg1[NODES * D1];
__device__ float g_h1  [NODES * D1];
__device__ float g_z2  [NODES * D2];
__device__ float g_agg2[NODES * D2];
__device__ float g_h2  [NODES * D2];
__device__ float g_agg3[NODES * D2];
__device__ float g_invdeg[NODES];
__device__ int   g_is64;
__device__ int   g_src[ED];
__device__ int   g_dst[ED];
__device__ int   g_deg[NODES];
__device__ int   g_row_ptr[NODES + 1];
__device__ int   g_blocksum[NBLK];
__device__ int   g_blockoff[NBLK];
__device__ int   g_cursor[NODES];
__device__ int   g_csr_src[ED];

// scratch buffer selector — device-side only, so no host symbol addresses
__device__ __forceinline__ float* scratch(int id) {
    switch (id) {
        case 0: return g_z1;
        case 1: return g_agg1;
        case 2: return g_h1;
        case 3: return g_z2;
        case 4: return g_agg2;
        case 5: return g_h2;
        case 6: return g_agg3;
    }
    return nullptr;
}

// ---------------------------------------------------------------------------
// Detect edge_index dtype. int64 little-endian: high 32-bit words are 0
// (values in [0, 50000)). int32: odd words are other indices, ~never 0.
__global__ void sniff_kernel(const void* __restrict__ ei) {
    if (threadIdx.x != 0 || blockIdx.x != 0) return;
    const unsigned* w = (const unsigned*)ei;
    int zeros = 0;
    for (int i = 0; i < 256; i++) zeros += (w[2 * i + 1] == 0u) ? 1 : 0;
    g_is64 = (zeros >= 128) ? 1 : 0;
}

__global__ void init_kernel() {
    int i = blockIdx.x * blockDim.x + threadIdx.x;
    if (i < NODES) g_deg[i] = 0;
}

// decode edge_index (either dtype); defensive clamp; count in-degree.
__global__ void edge_prep_kernel(const void* __restrict__ ei) {
    int e = blockIdx.x * blockDim.x + threadIdx.x;
    if (e >= ED) return;
    int s, d;
    if (g_is64) {
        const long long* p = (const long long*)ei;
        s = (int)p[e];
        d = (int)p[ED + e];
    } else {
        const int* p = (const int*)ei;
        s = p[e];
        d = p[ED + e];
    }
    s = min(max(s, 0), NODES - 1);
    d = min(max(d, 0), NODES - 1);
    g_src[e] = s;
    g_dst[e] = d;
    atomicAdd(&g_deg[d], 1);
}

// per-block exclusive scan of degrees; emit block totals
__global__ void scan_local_kernel() {
    __shared__ int sm[SCAN_B];
    int tid = threadIdx.x;
    int i = blockIdx.x * SCAN_B + tid;
    int v = (i < NODES) ? g_deg[i] : 0;
    sm[tid] = v;
    __syncthreads();
    for (int off = 1; off < SCAN_B; off <<= 1) {
        int t = (tid >= off) ? sm[tid - off] : 0;
        __syncthreads();
        sm[tid] += t;
        __syncthreads();
    }
    if (i < NODES) g_row_ptr[i] = sm[tid] - v;        // local exclusive
    if (tid == SCAN_B - 1) g_blocksum[blockIdx.x] = sm[tid];
}

// single-block scan of the block sums (NBLK <= 256)
__global__ void scan_blocksums_kernel() {
    __shared__ int sm[SCAN_B];
    int tid = threadIdx.x;
    int v = (tid < NBLK) ? g_blocksum[tid] : 0;
    sm[tid] = v;
    __syncthreads();
    for (int off = 1; off < SCAN_B; off <<= 1) {
        int t = (tid >= off) ? sm[tid - off] : 0;
        __syncthreads();
        sm[tid] += t;
        __syncthreads();
    }
    if (tid < NBLK) g_blockoff[tid] = sm[tid] - v;    // exclusive
}

// finalize row_ptr, init cursor, compute invdeg
__global__ void scan_add_kernel() {
    int i = blockIdx.x * blockDim.x + threadIdx.x;
    if (i >= NODES) return;
    int rp = g_row_ptr[i] + g_blockoff[i / SCAN_B];
    g_row_ptr[i] = rp;
    g_cursor[i]  = rp;
    g_invdeg[i]  = 1.0f / fmaxf((float)g_deg[i], 1.0f);
    if (i == 0) g_row_ptr[NODES] = ED;
}

// scatter src ids into CSR slots (int atomics)
__global__ void scatter_kernel() {
    int e = blockIdx.x * blockDim.x + threadIdx.x;
    if (e >= ED) return;
    int pos = atomicAdd(&g_cursor[g_dst[e]], 1);
    g_csr_src[pos] = g_src[e];
}

// ---------------------------------------------------------------------------
// Mean-gather: one block per node, thread j accumulates column j over the
// node's in-edges. Coalesced reads, register accumulation, no atomics.
__global__ void gather_kernel(int src_id, int dst_id, int D) {
    const float* Z   = scratch(src_id);
    float*       AGG = scratch(dst_id);
    int n = blockIdx.x;
    int j = threadIdx.x;
    if (j >= D) return;
    int beg = g_row_ptr[n];
    int end = g_row_ptr[n + 1];
    float acc = 0.0f;
    for (int i = beg; i < end; i++) {
        int s = g_csr_src[i];                 // broadcast load
        acc += Z[(size_t)s * D + j];          // coalesced across j
    }
    AGG[(size_t)n * D + j] = acc * g_invdeg[n];
}

// ---------------------------------------------------------------------------
// Fused linear: 4 node-rows per block, thread j = output column.
//   out[n,j] = act( (A1@W1)[n,j] + (A2@W2)[n,j] + C[n,j] + bias[j] )
// A ids >= 0 select scratch buffers; a1_ext supplies harness input x.
// out_id >= 0 selects scratch; else writes to oext.
__global__ void lin_kernel(const float* __restrict__ a1_ext, int a1_id, int lda1,
                           const float* __restrict__ W1, int K1,
                           int a2_id, int lda2,
                           const float* __restrict__ W2, int K2,
                           int c_id, int ldc,
                           const float* __restrict__ bias, int has_bias,
                           float* __restrict__ oext, int out_id,
                           int ldo, int DO, int relu)
{
    __shared__ float sA1[4 * 128];
    __shared__ float sA2[4 * 64];
    const float* A1 = (a1_id >= 0) ? scratch(a1_id) : a1_ext;
    const float* A2 = (a2_id >= 0) ? scratch(a2_id) : nullptr;
    const float* C  = (c_id  >= 0) ? scratch(c_id)  : nullptr;
    float* out = (out_id >= 0) ? scratch(out_id) : oext;

    int n0  = blockIdx.x * 4;
    int tid = threadIdx.x;
    int nt  = blockDim.x;

    for (int i = tid; i < 4 * K1; i += nt) {
        int r = i / K1, k = i - r * K1;
        sA1[r * K1 + k] = A1[(size_t)(n0 + r) * lda1 + k];
    }
    if (A2) {
        for (int i = tid; i < 4 * K2; i += nt) {
            int r = i / K2, k = i - r * K2;
            sA2[r * K2 + k] = A2[(size_t)(n0 + r) * lda2 + k];
        }
    }
    __syncthreads();

    int j = tid;
    if (j >= DO) return;

    float acc0 = 0.f, acc1 = 0.f, acc2 = 0.f, acc3 = 0.f;
    for (int k = 0; k < K1; k++) {
        float w = W1[k * DO + j];             // coalesced across j
        acc0 += sA1[0 * K1 + k] * w;
        acc1 += sA1[1 * K1 + k] * w;
        acc2 += sA1[2 * K1 + k] * w;
        acc3 += sA1[3 * K1 + k] * w;
    }
    if (A2) {
        for (int k = 0; k < K2; k++) {
            float w = W2[k * DO + j];
            acc0 += sA2[0 * K2 + k] * w;
            acc1 += sA2[1 * K2 + k] * w;
            acc2 += sA2[2 * K2 + k] * w;
            acc3 += sA2[3 * K2 + k] * w;
        }
    }

    float b = has_bias ? bias[j] : 0.0f;
    float v0 = acc0 + b, v1 = acc1 + b, v2 = acc2 + b, v3 = acc3 + b;
    if (C) {
        v0 += C[(size_t)(n0 + 0) * ldc + j];
        v1 += C[(size_t)(n0 + 1) * ldc + j];
        v2 += C[(size_t)(n0 + 2) * ldc + j];
        v3 += C[(size_t)(n0 + 3) * ldc + j];
    }
    if (relu) {
        v0 = fmaxf(v0, 0.f); v1 = fmaxf(v1, 0.f);
        v2 = fmaxf(v2, 0.f); v3 = fmaxf(v3, 0.f);
    }
    out[(size_t)(n0 + 0) * ldo + j] = v0;
    out[(size_t)(n0 + 1) * ldo + j] = v1;
    out[(size_t)(n0 + 2) * ldo + j] = v2;
    out[(size_t)(n0 + 3) * ldo + j] = v3;
}

// ---------------------------------------------------------------------------
extern "C" void kernel_launch(void* const* d_in, const int* in_sizes, int n_in,
                              void* d_out, int out_size) {
    const float* x    = (const float*)d_in[0];
    const void*  ei   = (const void*)d_in[1];
    const float* Wl1  = (const float*)d_in[2];
    const float* Wr1  = (const float*)d_in[3];
    const float* b1   = (const float*)d_in[4];
    const float* Wl2  = (const float*)d_in[5];
    const float* Wr2  = (const float*)d_in[6];
    const float* b2   = (const float*)d_in[7];
    const float* Wlmu = (const float*)d_in[8];
    const float* Wrmu = (const float*)d_in[9];
    const float* bmu  = (const float*)d_in[10];
    const float* Wllv = (const float*)d_in[11];
    const float* Wrlv = (const float*)d_in[12];
    const float* blv  = (const float*)d_in[13];
    float* out = (float*)d_out;

    const int NB    = (NODES + 255) / 256;
    const int EB    = (ED + 255) / 256;
    const int LGRID = NODES / 4;              // 12500, exact

    // ---- CSR build ----
    sniff_kernel<<<1, 32>>>(ei);
    init_kernel<<<NB, 256>>>();
    edge_prep_kernel<<<EB, 256>>>(ei);
    scan_local_kernel<<<NBLK, SCAN_B>>>();
    scan_blocksums_kernel<<<1, SCAN_B>>>();
    scan_add_kernel<<<NB, 256>>>();
    scatter_kernel<<<EB, 256>>>();

    // z1 = x @ Wl1                      -> scratch 0
    lin_kernel<<<LGRID, 128>>>(x, -1, IN_D, Wl1, IN_D,
                               -1, 0, nullptr, 0,
                               -1, 0, nullptr, 0,
                               nullptr, 0, D1, D1, 0);

    // agg1 = mean-gather(z1)            0 -> 1
    gather_kernel<<<NODES, 128>>>(0, 1, D1);

    // h1 = relu(x @ Wr1 + agg1 + b1)   -> scratch 2
    lin_kernel<<<LGRID, 128>>>(x, -1, IN_D, Wr1, IN_D,
                               -1, 0, nullptr, 0,
                               1, D1, b1, 1,
                               nullptr, 2, D1, D1, 1);

    // z2 = h1 @ Wl2                    -> scratch 3
    lin_kernel<<<LGRID, 64>>>(nullptr, 2, D1, Wl2, D1,
                              -1, 0, nullptr, 0,
                              -1, 0, nullptr, 0,
                              nullptr, 3, D2, D2, 0);

    // agg2 = mean-gather(z2)            3 -> 4
    gather_kernel<<<NODES, 64>>>(3, 4, D2);

    // h2 = relu(h1 @ Wr2 + agg2 + b2)  -> scratch 5
    lin_kernel<<<LGRID, 64>>>(nullptr, 2, D1, Wr2, D1,
                              -1, 0, nullptr, 0,
                              4, D2, b2, 1,
                              nullptr, 5, D2, D2, 1);

    // agg3 = mean-gather(h2)            5 -> 6
    gather_kernel<<<NODES, 64>>>(5, 6, D2);

    // mu = agg3 @ Wlmu + h2 @ Wrmu + bmu   -> out[0..]
    lin_kernel<<<LGRID, 32>>>(nullptr, 6, D2, Wlmu, D2,
                              5, D2, Wrmu, D2,
                              -1, 0, bmu, 1,
                              out, -1, DOUT, DOUT, 0);

    // lv = agg3 @ Wllv + h2 @ Wrlv + blv   -> out[NODES*DOUT..]
    lin_kernel<<<LGRID, 32>>>(nullptr, 6, D2, Wllv, D2,
                              5, D2, Wrlv, D2,
                              -1, 0, blv, 1,
                              out + (size_t)NODES * DOUT, -1, DOUT, DOUT, 0);
}